// round 11
// baseline (speedup 1.0000x reference)
#include <cuda_runtime.h>

#define IMG_W 512
#define IMG_H 512
#define PLANES 64
#define PLANE_STRIDE (IMG_H * IMG_W)
#define NPIX (PLANES * PLANE_STRIDE)
#define STRIP 16
#define STRIPS (IMG_H / STRIP)          // 32
#define NBLOCKS (PLANES * STRIPS)       // 2048
#define EPS 1e-10f

// persistent scratch (statically zero-initialized; reset by last block each call)
__device__ double g_acc;
__device__ unsigned int g_count;

__global__ void __launch_bounds__(64) ngf_kernel(
    const float* __restrict__ I0, const float* __restrict__ I1,
    float* __restrict__ out)
{
    const int t     = threadIdx.x;            // 0..63, 8 cols per thread
    const int lane  = t & 31;
    const int plane = blockIdx.x >> 5;        // / STRIPS
    const int strip = blockIdx.x & (STRIPS - 1);
    const int col   = t << 3;                 // 0..504

    const float* __restrict__ p0 = I0 + plane * PLANE_STRIDE + col;
    const float* __restrict__ p1 = I1 + plane * PLANE_STRIDE + col;

    const int rbase = strip * STRIP;
    const int rup   = (rbase > 0) ? rbase - 1 : 0;
    const int rdn   = rbase + 1;              // <= 497, in range

    // rolling rows: each row = 2 float4 per image (8 cols)
    float4 up0a = *(const float4*)(p0 + rup * IMG_W);
    float4 up0b = *(const float4*)(p0 + rup * IMG_W + 4);
    float4 up1a = *(const float4*)(p1 + rup * IMG_W);
    float4 up1b = *(const float4*)(p1 + rup * IMG_W + 4);
    float4 ce0a = *(const float4*)(p0 + rbase * IMG_W);
    float4 ce0b = *(const float4*)(p0 + rbase * IMG_W + 4);
    float4 ce1a = *(const float4*)(p1 + rbase * IMG_W);
    float4 ce1b = *(const float4*)(p1 + rbase * IMG_W + 4);
    float4 dn0a = *(const float4*)(p0 + rdn * IMG_W);
    float4 dn0b = *(const float4*)(p0 + rdn * IMG_W + 4);
    float4 dn1a = *(const float4*)(p1 + rdn * IMG_W);
    float4 dn1b = *(const float4*)(p1 + rdn * IMG_W + 4);

    const float* pr0 = p0 + rbase * IMG_W;    // current-row pointers (halo scalars)
    const float* pr1 = p1 + rbase * IMG_W;

    // edge flags: t==0 left image edge; t==63 right image edge.
    // lane 0 / lane 31 of the other warp patch from global (L1/L2 hit).
    const bool leftEdge  = (col == 0);
    const bool rightEdge = (col + 8 == IMG_W);

    float s0 = 0.f, s1 = 0.f;

#pragma unroll 4
    for (int r = rbase; r < rbase + STRIP; ++r) {
        // 1-row lookahead (clamped at bottom)
        int rn = r + 2;
        if (rn > IMG_H - 1) rn = IMG_H - 1;
        const float* q0 = p0 + rn * IMG_W;
        const float* q1 = p1 + rn * IMG_W;
        const float4 n0a = *(const float4*)(q0);
        const float4 n0b = *(const float4*)(q0 + 4);
        const float4 n1a = *(const float4*)(q1);
        const float4 n1b = *(const float4*)(q1 + 4);

        // horizontal halo (cols col-1 and col+8): shfl within warp;
        // lane-edge threads patch from global (warp boundary / image edge)
        float hl0 = __shfl_up_sync(0xFFFFFFFFu, ce0b.w, 1);
        float hr0 = __shfl_down_sync(0xFFFFFFFFu, ce0a.x, 1);
        float hl1 = __shfl_up_sync(0xFFFFFFFFu, ce1b.w, 1);
        float hr1 = __shfl_down_sync(0xFFFFFFFFu, ce1a.x, 1);
        if (lane == 0) {
            hl0 = leftEdge ? ce0a.x : pr0[-1];
            hl1 = leftEdge ? ce1a.x : pr1[-1];
        }
        if (lane == 31) {
            hr0 = rightEdge ? ce0b.w : pr0[8];
            hr1 = rightEdge ? ce1b.w : pr1[8];
        }

        // gx = x[min(r+1)] - x[max(r-1)]   (fwd/central/bwd diff)
        const float g0x[8] = { dn0a.x-up0a.x, dn0a.y-up0a.y, dn0a.z-up0a.z, dn0a.w-up0a.w,
                               dn0b.x-up0b.x, dn0b.y-up0b.y, dn0b.z-up0b.z, dn0b.w-up0b.w };
        const float g1x[8] = { dn1a.x-up1a.x, dn1a.y-up1a.y, dn1a.z-up1a.z, dn1a.w-up1a.w,
                               dn1b.x-up1b.x, dn1b.y-up1b.y, dn1b.z-up1b.z, dn1b.w-up1b.w };
        // gy = x[min(c+1)] - x[max(c-1)] : 6 of 8 neighbors in-register
        const float g0y[8] = { ce0a.y-hl0,    ce0a.z-ce0a.x, ce0a.w-ce0a.y, ce0b.x-ce0a.z,
                               ce0b.y-ce0a.w, ce0b.z-ce0b.x, ce0b.w-ce0b.y, hr0-ce0b.z };
        const float g1y[8] = { ce1a.y-hl1,    ce1a.z-ce1a.x, ce1a.w-ce1a.y, ce1b.x-ce1a.z,
                               ce1b.y-ce1a.w, ce1b.z-ce1b.x, ce1b.w-ce1b.y, hr1-ce1b.z };

#pragma unroll
        for (int i = 0; i < 8; i++) {
            const float n0  = fmaf(g0x[i], g0x[i], fmaf(g0y[i], g0y[i], EPS));
            const float n1  = fmaf(g1x[i], g1x[i], fmaf(g1y[i], g1y[i], EPS));
            const float dot = fmaf(g0x[i], g1x[i], g0y[i] * g1y[i]);
            // dot^2/(n0*n1) == (g0/|g0| . g1/|g1|)^2
            const float v = __fdividef(dot * dot, n0 * n1);
            if (i & 1) s1 += v; else s0 += v;
        }

        // rotate rows, advance halo pointers
        up0a = ce0a; up0b = ce0b; up1a = ce1a; up1b = ce1b;
        ce0a = dn0a; ce0b = dn0b; ce1a = dn1a; ce1b = dn1b;
        dn0a = n0a;  dn0b = n0b;  dn1a = n1a;  dn1b = n1b;
        pr0 += IMG_W; pr1 += IMG_W;
    }

    float s = s0 + s1;

    // warp reduction (2 warps)
#pragma unroll
    for (int off = 16; off > 0; off >>= 1)
        s += __shfl_xor_sync(0xFFFFFFFFu, s, off);

    __shared__ float warp_part[2];
    const int wid = t >> 5;
    if (lane == 0) warp_part[wid] = s;
    __syncthreads();

    if (t == 0) {
        const double bs = (double)warp_part[0] + (double)warp_part[1];
        atomicAdd(&g_acc, bs);
        __threadfence();
        const unsigned prev = atomicAdd(&g_count, 1u);
        if (prev == NBLOCKS - 1) {
            // last block: all adds visible (atomics serialize at L2)
            const double total = atomicAdd(&g_acc, 0.0);
            out[0] = (float)(1.0 - total / (double)NPIX);
            // reset for next graph replay (deterministic)
            g_acc = 0.0;
            g_count = 0u;
            __threadfence();
        }
    }
}

extern "C" void kernel_launch(void* const* d_in, const int* in_sizes, int n_in,
                              void* d_out, int out_size)
{
    const float* I0 = (const float*)d_in[0];
    const float* I1 = (const float*)d_in[1];
    float* out = (float*)d_out;

    ngf_kernel<<<NBLOCKS, 64>>>(I0, I1, out);
}

// round 12
// speedup vs baseline: 1.0611x; 1.0611x over previous
#include <cuda_runtime.h>

#define IMG_W 512
#define IMG_H 512
#define PLANES 64
#define PLANE_STRIDE (IMG_H * IMG_W)
#define NPIX (PLANES * PLANE_STRIDE)
#define STRIP 16
#define STRIPS (IMG_H / STRIP)          // 32
#define NBLOCKS (PLANES * STRIPS)       // 2048
#define EPS 1e-10f

// persistent scratch (statically zero-initialized; reset by last block each call)
__device__ double g_acc;
__device__ unsigned int g_count;

__global__ void __launch_bounds__(128) ngf_kernel(
    const float* __restrict__ I0, const float* __restrict__ I1,
    float* __restrict__ out)
{
    const int t     = threadIdx.x;            // 0..127, one float4 column-group
    const int lane  = t & 31;
    const int plane = blockIdx.x >> 5;        // / STRIPS
    const int strip = blockIdx.x & (STRIPS - 1);
    const int col   = t << 2;                 // 0..508
    const int rbase = strip * STRIP;

    const float* __restrict__ p0 = I0 + plane * PLANE_STRIDE + col;
    const float* __restrict__ p1 = I1 + plane * PLANE_STRIDE + col;

    // halo scalar base: row rbase; all accesses use compile-time immediate offsets
    const float* __restrict__ h0 = p0 + rbase * IMG_W;
    const float* __restrict__ h1 = p1 + rbase * IMG_W;

    const bool leftEdge  = (col == 0);
    const bool rightEdge = (col + 4 == IMG_W);

    // 5-slot static ring: slot (k%5) holds row rbase-1+k (rows clamped to [0,511]).
    // Full unroll => all indices compile-time => zero rotation MOVs at SASS level.
    float4 r0[5], r1[5];

    // prologue: k = 0..3  (rows rbase-1 .. rbase+2)
    {
        const int g = (rbase > 0) ? rbase - 1 : 0;
        r0[0] = *(const float4*)(p0 + g * IMG_W);
        r1[0] = *(const float4*)(p1 + g * IMG_W);
    }
#pragma unroll
    for (int k = 1; k < 4; k++) {
        const int g = rbase - 1 + k;          // <= 498: no clamp needed
        r0[k] = *(const float4*)(p0 + g * IMG_W);
        r1[k] = *(const float4*)(p1 + g * IMG_W);
    }

    float sA = 0.f, sB = 0.f;

#pragma unroll
    for (int i = 0; i < 16; i++) {
        // lookahead-2: load k = i+4 (row rbase+i+3, clamped) into slot (i+4)%5.
        // Slot (i+4)%5 == (i-1)%5 last read at iteration i-1 -> safe.
        if (i <= 13) {                         // constant per unrolled iter
            int g = rbase + i + 3;
            if (g > IMG_H - 1) g = IMG_H - 1;  // only binds for strip 31
            r0[(i + 4) % 5] = *(const float4*)(p0 + g * IMG_W);
            r1[(i + 4) % 5] = *(const float4*)(p1 + g * IMG_W);
        }

        const float4 up0 = r0[i % 5],       up1 = r1[i % 5];
        const float4 ce0 = r0[(i + 1) % 5], ce1 = r1[(i + 1) % 5];
        const float4 dn0 = r0[(i + 2) % 5], dn1 = r1[(i + 2) % 5];

        // horizontal halo: shfl interior; warp-edge lanes patch via
        // immediate-offset scalar loads (compile-time i*IMG_W +/- 1)
        float hl0 = __shfl_up_sync(0xFFFFFFFFu, ce0.w, 1);
        float hr0 = __shfl_down_sync(0xFFFFFFFFu, ce0.x, 1);
        float hl1 = __shfl_up_sync(0xFFFFFFFFu, ce1.w, 1);
        float hr1 = __shfl_down_sync(0xFFFFFFFFu, ce1.x, 1);
        if (lane == 0) {
            hl0 = leftEdge ? ce0.x : h0[i * IMG_W - 1];
            hl1 = leftEdge ? ce1.x : h1[i * IMG_W - 1];
        }
        if (lane == 31) {
            hr0 = rightEdge ? ce0.w : h0[i * IMG_W + 4];
            hr1 = rightEdge ? ce1.w : h1[i * IMG_W + 4];
        }

        // gx = x[min(r+1)] - x[max(r-1)]   (fwd/central/bwd diff; rows clamped)
        const float g0x[4] = { dn0.x - up0.x, dn0.y - up0.y, dn0.z - up0.z, dn0.w - up0.w };
        const float g1x[4] = { dn1.x - up1.x, dn1.y - up1.y, dn1.z - up1.z, dn1.w - up1.w };
        // gy = x[min(c+1)] - x[max(c-1)]
        const float g0y[4] = { ce0.y - hl0, ce0.z - ce0.x, ce0.w - ce0.y, hr0 - ce0.z };
        const float g1y[4] = { ce1.y - hl1, ce1.z - ce1.x, ce1.w - ce1.y, hr1 - ce1.z };

#pragma unroll
        for (int q = 0; q < 4; q++) {
            const float n0  = fmaf(g0x[q], g0x[q], fmaf(g0y[q], g0y[q], EPS));
            const float n1  = fmaf(g1x[q], g1x[q], fmaf(g1y[q], g1y[q], EPS));
            const float dot = fmaf(g0x[q], g1x[q], g0y[q] * g1y[q]);
            // dot^2/(n0*n1) == (g0/|g0| . g1/|g1|)^2
            const float v = __fdividef(dot * dot, n0 * n1);
            if (q & 1) sB += v; else sA += v;
        }
    }

    float s = sA + sB;

    // warp reduction
#pragma unroll
    for (int off = 16; off > 0; off >>= 1)
        s += __shfl_xor_sync(0xFFFFFFFFu, s, off);

    __shared__ float warp_part[4];
    const int wid = t >> 5;
    if (lane == 0) warp_part[wid] = s;
    __syncthreads();

    if (t == 0) {
        const double bs = (double)warp_part[0] + (double)warp_part[1]
                        + (double)warp_part[2] + (double)warp_part[3];
        atomicAdd(&g_acc, bs);
        __threadfence();
        const unsigned prev = atomicAdd(&g_count, 1u);
        if (prev == NBLOCKS - 1) {
            // last block: all adds visible (atomics serialize at L2)
            const double total = atomicAdd(&g_acc, 0.0);
            out[0] = (float)(1.0 - total / (double)NPIX);
            // reset for next graph replay (deterministic)
            g_acc = 0.0;
            g_count = 0u;
            __threadfence();
        }
    }
}

extern "C" void kernel_launch(void* const* d_in, const int* in_sizes, int n_in,
                              void* d_out, int out_size)
{
    const float* I0 = (const float*)d_in[0];
    const float* I1 = (const float*)d_in[1];
    float* out = (float*)d_out;

    ngf_kernel<<<NBLOCKS, 128>>>(I0, I1, out);
}

// round 13
// speedup vs baseline: 1.2180x; 1.1479x over previous
#include <cuda_runtime.h>

#define IMG_W 512
#define IMG_H 512
#define PLANES 64
#define PLANE_STRIDE (IMG_H * IMG_W)
#define NPIX (PLANES * PLANE_STRIDE)
#define STRIP 16
#define STRIPS (IMG_H / STRIP)          // 32
#define NBLOCKS (PLANES * STRIPS)       // 2048
#define EPS 1e-10f

// persistent scratch (statically zero-initialized; reset by last block each call)
__device__ double g_acc;
__device__ unsigned int g_count;

// evict-first streaming load of a float4 row segment (no reuse after 3-row window)
__device__ __forceinline__ float4 ldcs4(const float* p) {
    return __ldcs((const float4*)p);
}

__device__ __forceinline__ float process_row(
    const float4& up0, const float4& cen0, const float4& dn0,
    const float4& up1, const float4& cen1, const float4& dn1,
    const float* pr0, const float* pr1,
    bool leftEdge, bool rightEdge, int lane)
{
    // horizontal halo: neighbor lanes via shfl; warp-edge lanes patch with
    // an (L1/L2-hit) scalar load, clamped at image edge
    float hl0 = __shfl_up_sync(0xFFFFFFFFu, cen0.w, 1);
    float hr0 = __shfl_down_sync(0xFFFFFFFFu, cen0.x, 1);
    float hl1 = __shfl_up_sync(0xFFFFFFFFu, cen1.w, 1);
    float hr1 = __shfl_down_sync(0xFFFFFFFFu, cen1.x, 1);
    if (lane == 0) {
        hl0 = leftEdge ? cen0.x : __ldg(pr0 - 1);
        hl1 = leftEdge ? cen1.x : __ldg(pr1 - 1);
    }
    if (lane == 31) {
        hr0 = rightEdge ? cen0.w : __ldg(pr0 + 4);
        hr1 = rightEdge ? cen1.w : __ldg(pr1 + 4);
    }

    // gx = x[min(r+1)] - x[max(r-1)]   (fwd/central/bwd diff)
    const float g0x[4] = { dn0.x - up0.x, dn0.y - up0.y, dn0.z - up0.z, dn0.w - up0.w };
    const float g1x[4] = { dn1.x - up1.x, dn1.y - up1.y, dn1.z - up1.z, dn1.w - up1.w };
    // gy = x[min(c+1)] - x[max(c-1)]
    const float g0y[4] = { cen0.y - hl0, cen0.z - cen0.x, cen0.w - cen0.y, hr0 - cen0.z };
    const float g1y[4] = { cen1.y - hl1, cen1.z - cen1.x, cen1.w - cen1.y, hr1 - cen1.z };

    float a = 0.f, b = 0.f;
#pragma unroll
    for (int i = 0; i < 4; i++) {
        const float n0  = fmaf(g0x[i], g0x[i], fmaf(g0y[i], g0y[i], EPS));
        const float n1  = fmaf(g1x[i], g1x[i], fmaf(g1y[i], g1y[i], EPS));
        const float dot = fmaf(g0x[i], g1x[i], g0y[i] * g1y[i]);
        // dot^2/(n0*n1) == (g0/|g0| . g1/|g1|)^2
        const float v = __fdividef(dot * dot, n0 * n1);
        if (i & 1) b += v; else a += v;
    }
    return a + b;
}

__global__ void __launch_bounds__(128) ngf_kernel(
    const float* __restrict__ I0, const float* __restrict__ I1,
    float* __restrict__ out)
{
    const int t     = threadIdx.x;            // 0..127, one float4 column-group
    const int lane  = t & 31;
    const int plane = blockIdx.x >> 5;        // / STRIPS
    const int strip = blockIdx.x & (STRIPS - 1);
    const int col   = t << 2;                 // 0..508

    const float* __restrict__ p0 = I0 + plane * PLANE_STRIDE + col;
    const float* __restrict__ p1 = I1 + plane * PLANE_STRIDE + col;

    const int rbase = strip * STRIP;
    const int rup   = (rbase > 0) ? rbase - 1 : 0;
    const int rdn   = rbase + 1;              // <= 497, always in range

    // rolling rows: up = row max(r-1,0), cen = row r, dn = row min(r+1,511)
    float4 up0  = ldcs4(p0 + rup * IMG_W);
    float4 up1  = ldcs4(p1 + rup * IMG_W);
    float4 cen0 = ldcs4(p0 + rbase * IMG_W);
    float4 cen1 = ldcs4(p1 + rbase * IMG_W);
    float4 dn0  = ldcs4(p0 + rdn * IMG_W);
    float4 dn1  = ldcs4(p1 + rdn * IMG_W);

    const float* pr0 = p0 + rbase * IMG_W;    // current-row pointers (halo scalars)
    const float* pr1 = p1 + rbase * IMG_W;

    const bool leftEdge  = (col == 0);
    const bool rightEdge = (col + 4 == IMG_W);

    float s = 0.f;

    // process 2 rows per iteration; batch-load rows r+2, r+3 (front-batched MLP=4)
#pragma unroll 2
    for (int r = rbase; r < rbase + STRIP; r += 2) {
        int rnA = r + 2; if (rnA > IMG_H - 1) rnA = IMG_H - 1;
        int rnB = r + 3; if (rnB > IMG_H - 1) rnB = IMG_H - 1;
        const float4 nA0 = ldcs4(p0 + rnA * IMG_W);
        const float4 nA1 = ldcs4(p1 + rnA * IMG_W);
        const float4 nB0 = ldcs4(p0 + rnB * IMG_W);
        const float4 nB1 = ldcs4(p1 + rnB * IMG_W);

        s += process_row(up0, cen0, dn0, up1, cen1, dn1,
                         pr0, pr1, leftEdge, rightEdge, lane);
        up0 = cen0; cen0 = dn0; dn0 = nA0;
        up1 = cen1; cen1 = dn1; dn1 = nA1;
        pr0 += IMG_W; pr1 += IMG_W;

        s += process_row(up0, cen0, dn0, up1, cen1, dn1,
                         pr0, pr1, leftEdge, rightEdge, lane);
        up0 = cen0; cen0 = dn0; dn0 = nB0;
        up1 = cen1; cen1 = dn1; dn1 = nB1;
        pr0 += IMG_W; pr1 += IMG_W;
    }

    // warp reduction
#pragma unroll
    for (int off = 16; off > 0; off >>= 1)
        s += __shfl_xor_sync(0xFFFFFFFFu, s, off);

    __shared__ float warp_part[4];
    const int wid = t >> 5;
    if (lane == 0) warp_part[wid] = s;
    __syncthreads();

    if (t == 0) {
        const double bs = (double)warp_part[0] + (double)warp_part[1]
                        + (double)warp_part[2] + (double)warp_part[3];
        atomicAdd(&g_acc, bs);
        __threadfence();
        const unsigned prev = atomicAdd(&g_count, 1u);
        if (prev == NBLOCKS - 1) {
            // last block: all adds visible (atomics serialize at L2)
            const double total = atomicAdd(&g_acc, 0.0);
            out[0] = (float)(1.0 - total / (double)NPIX);
            // reset for next graph replay (deterministic)
            g_acc = 0.0;
            g_count = 0u;
            __threadfence();
        }
    }
}

extern "C" void kernel_launch(void* const* d_in, const int* in_sizes, int n_in,
                              void* d_out, int out_size)
{
    const float* I0 = (const float*)d_in[0];
    const float* I1 = (const float*)d_in[1];
    float* out = (float*)d_out;

    ngf_kernel<<<NBLOCKS, 128>>>(I0, I1, out);
}

// round 14
// speedup vs baseline: 1.2369x; 1.0156x over previous
#include <cuda_runtime.h>

#define IMG_W 512
#define IMG_H 512
#define PLANES 64
#define PLANE_STRIDE (IMG_H * IMG_W)
#define NPIX (PLANES * PLANE_STRIDE)
#define STRIP 16
#define STRIPS (IMG_H / STRIP)          // 32
#define NBLOCKS (PLANES * STRIPS)       // 2048
#define EPS 1e-10f

// persistent scratch (statically zero-initialized; reset by last block each call)
__device__ double g_acc;
__device__ unsigned int g_count;

// evict-first streaming load (row data dead after its 3-row window)
__device__ __forceinline__ float4 ldcs4(const float* p) {
    return __ldcs((const float4*)p);
}

__device__ __forceinline__ float process_row(
    const float4& up0, const float4& cen0, const float4& dn0,
    const float4& up1, const float4& cen1, const float4& dn1,
    const float* pr0, const float* pr1,
    bool leftEdge, bool rightEdge, int lane)
{
    // horizontal halo: neighbor lanes via shfl; warp-edge lanes patch with
    // an (L1/L2-hit) scalar load, clamped at image edge
    float hl0 = __shfl_up_sync(0xFFFFFFFFu, cen0.w, 1);
    float hr0 = __shfl_down_sync(0xFFFFFFFFu, cen0.x, 1);
    float hl1 = __shfl_up_sync(0xFFFFFFFFu, cen1.w, 1);
    float hr1 = __shfl_down_sync(0xFFFFFFFFu, cen1.x, 1);
    if (lane == 0) {
        hl0 = leftEdge ? cen0.x : __ldg(pr0 - 1);
        hl1 = leftEdge ? cen1.x : __ldg(pr1 - 1);
    }
    if (lane == 31) {
        hr0 = rightEdge ? cen0.w : __ldg(pr0 + 4);
        hr1 = rightEdge ? cen1.w : __ldg(pr1 + 4);
    }

    // gx = x[min(r+1)] - x[max(r-1)]   (fwd/central/bwd diff)
    const float g0x[4] = { dn0.x - up0.x, dn0.y - up0.y, dn0.z - up0.z, dn0.w - up0.w };
    const float g1x[4] = { dn1.x - up1.x, dn1.y - up1.y, dn1.z - up1.z, dn1.w - up1.w };
    // gy = x[min(c+1)] - x[max(c-1)]
    const float g0y[4] = { cen0.y - hl0, cen0.z - cen0.x, cen0.w - cen0.y, hr0 - cen0.z };
    const float g1y[4] = { cen1.y - hl1, cen1.z - cen1.x, cen1.w - cen1.y, hr1 - cen1.z };

    float a = 0.f, b = 0.f;
#pragma unroll
    for (int i = 0; i < 4; i++) {
        const float n0  = fmaf(g0x[i], g0x[i], fmaf(g0y[i], g0y[i], EPS));
        const float n1  = fmaf(g1x[i], g1x[i], fmaf(g1y[i], g1y[i], EPS));
        const float dot = fmaf(g0x[i], g1x[i], g0y[i] * g1y[i]);
        // dot^2/(n0*n1) == (g0/|g0| . g1/|g1|)^2
        const float v = __fdividef(dot * dot, n0 * n1);
        if (i & 1) b += v; else a += v;
    }
    return a + b;
}

__global__ void __launch_bounds__(128) ngf_kernel(
    const float* __restrict__ I0, const float* __restrict__ I1,
    float* __restrict__ out)
{
    const int t     = threadIdx.x;            // 0..127, one float4 column-group
    const int lane  = t & 31;
    const int plane = blockIdx.x >> 5;        // / STRIPS
    const int strip = blockIdx.x & (STRIPS - 1);
    const int col   = t << 2;                 // 0..508

    const float* __restrict__ p0 = I0 + plane * PLANE_STRIDE + col;
    const float* __restrict__ p1 = I1 + plane * PLANE_STRIDE + col;

    const int rbase = strip * STRIP;
    const int rup   = (rbase > 0) ? rbase - 1 : 0;

    // rolling rows: up = row max(r-1,0), cen = row r, dn = row min(r+1,511)
    float4 up0  = ldcs4(p0 + rup * IMG_W);
    float4 up1  = ldcs4(p1 + rup * IMG_W);
    float4 cen0 = ldcs4(p0 + rbase * IMG_W);
    float4 cen1 = ldcs4(p1 + rbase * IMG_W);
    float4 dn0  = ldcs4(p0 + (rbase + 1) * IMG_W);
    float4 dn1  = ldcs4(p1 + (rbase + 1) * IMG_W);

    const bool leftEdge  = (col == 0);
    const bool rightEdge = (col + 4 == IMG_W);

    float s = 0.f;

    // current-row pointers (also the base for immediate-offset lookahead loads)
    const float* q0 = p0 + rbase * IMG_W;
    const float* q1 = p1 + rbase * IMG_W;

    if (strip != STRIPS - 1) {
        // FAST PATH (strips 0..30): rows r+2, r+3 <= 511 always in range.
        // All lookahead loads are immediate offsets: zero clamp, zero IMAD row math.
#pragma unroll 2
        for (int it = 0; it < STRIP / 2; ++it) {
            const float4 nA0 = ldcs4(q0 + 2 * IMG_W);
            const float4 nA1 = ldcs4(q1 + 2 * IMG_W);
            const float4 nB0 = ldcs4(q0 + 3 * IMG_W);
            const float4 nB1 = ldcs4(q1 + 3 * IMG_W);

            s += process_row(up0, cen0, dn0, up1, cen1, dn1,
                             q0, q1, leftEdge, rightEdge, lane);
            up0 = cen0; cen0 = dn0; dn0 = nA0;
            up1 = cen1; cen1 = dn1; dn1 = nA1;

            s += process_row(up0, cen0, dn0, up1, cen1, dn1,
                             q0 + IMG_W, q1 + IMG_W, leftEdge, rightEdge, lane);
            up0 = cen0; cen0 = dn0; dn0 = nB0;
            up1 = cen1; cen1 = dn1; dn1 = nB1;

            q0 += 2 * IMG_W; q1 += 2 * IMG_W;
        }
    } else {
        // GENERAL PATH (strip 31 only): bottom clamp needed on lookahead rows
#pragma unroll 2
        for (int r = rbase; r < rbase + STRIP; r += 2) {
            int rnA = r + 2; if (rnA > IMG_H - 1) rnA = IMG_H - 1;
            int rnB = r + 3; if (rnB > IMG_H - 1) rnB = IMG_H - 1;
            const float4 nA0 = ldcs4(p0 + rnA * IMG_W);
            const float4 nA1 = ldcs4(p1 + rnA * IMG_W);
            const float4 nB0 = ldcs4(p0 + rnB * IMG_W);
            const float4 nB1 = ldcs4(p1 + rnB * IMG_W);

            s += process_row(up0, cen0, dn0, up1, cen1, dn1,
                             q0, q1, leftEdge, rightEdge, lane);
            up0 = cen0; cen0 = dn0; dn0 = nA0;
            up1 = cen1; cen1 = dn1; dn1 = nA1;

            s += process_row(up0, cen0, dn0, up1, cen1, dn1,
                             q0 + IMG_W, q1 + IMG_W, leftEdge, rightEdge, lane);
            up0 = cen0; cen0 = dn0; dn0 = nB0;
            up1 = cen1; cen1 = dn1; dn1 = nB1;

            q0 += 2 * IMG_W; q1 += 2 * IMG_W;
        }
    }

    // warp reduction
#pragma unroll
    for (int off = 16; off > 0; off >>= 1)
        s += __shfl_xor_sync(0xFFFFFFFFu, s, off);

    __shared__ float warp_part[4];
    const int wid = t >> 5;
    if (lane == 0) warp_part[wid] = s;
    __syncthreads();

    if (t == 0) {
        const double bs = (double)warp_part[0] + (double)warp_part[1]
                        + (double)warp_part[2] + (double)warp_part[3];
        atomicAdd(&g_acc, bs);
        __threadfence();
        const unsigned prev = atomicAdd(&g_count, 1u);
        if (prev == NBLOCKS - 1) {
            // last block: all adds visible (atomics serialize at L2)
            const double total = atomicAdd(&g_acc, 0.0);
            out[0] = (float)(1.0 - total / (double)NPIX);
            // reset for next graph replay (deterministic)
            g_acc = 0.0;
            g_count = 0u;
            __threadfence();
        }
    }
}

extern "C" void kernel_launch(void* const* d_in, const int* in_sizes, int n_in,
                              void* d_out, int out_size)
{
    const float* I0 = (const float*)d_in[0];
    const float* I1 = (const float*)d_in[1];
    float* out = (float*)d_out;

    ngf_kernel<<<NBLOCKS, 128>>>(I0, I1, out);
}